// round 1
// baseline (speedup 1.0000x reference)
#include <cuda_runtime.h>
#include <cstdint>

// Problem constants
#define BB 2
#define SS 4096
#define HH 512
#define GG 18
#define NHEAD 8
#define DD 64
#define GH (GG*HH)        // 9216
#define MTOK (BB*SS)      // 8192
#define KDIM (NHEAD*DD)   // 512

// ---------- static device scratch (no allocations allowed) ----------
__device__ float g_A[(size_t)MTOK * GH];      // gathered input, 302 MB
__device__ float g_key[(size_t)MTOK * GH];    // 302 MB
__device__ float g_val[(size_t)MTOK * GH];    // 302 MB
__device__ float g_q[(size_t)MTOK * HH];      // 16 MB
__device__ float g_attn[(size_t)MTOK * HH];   // 16 MB
__device__ int   g_is64;

// ---------- detect whether connections buffer is int64 or int32 ----------
__global__ void detect_kernel(const int* __restrict__ conn) {
    if (threadIdx.x == 0 && blockIdx.x == 0) {
        int is64 = 1;
        #pragma unroll
        for (int i = 0; i < 64; i++) {
            if (conn[2 * i + 1] != 0) { is64 = 0; break; }
        }
        g_is64 = is64;
    }
}

// ---------- gather: A[bs, g*H + h] = hidden[b, clip(conn[bs,g]), h] ----------
__global__ void gather_kernel(const float4* __restrict__ hidden,
                              const void* __restrict__ conn,
                              float4* __restrict__ A) {
    size_t t = (size_t)blockIdx.x * blockDim.x + threadIdx.x;
    const size_t total = (size_t)MTOK * GG * (HH / 4);
    if (t >= total) return;
    int h4 = (int)(t & 127);            // HH/4 = 128
    size_t row = t >> 7;                // bs*G + g
    size_t bs = row / GG;
    int b = (int)(bs / SS);
    long long c;
    if (g_is64) c = ((const long long*)conn)[row];
    else        c = (long long)((const int*)conn)[row];
    float4 v = make_float4(0.f, 0.f, 0.f, 0.f);
    if (c >= 0) {
        if (c > SS - 1) c = SS - 1;
        v = hidden[((size_t)b * SS + (size_t)c) * (HH / 4) + h4];
    }
    A[t] = v;
}

// ---------- fp32 SIMT GEMM: C[M,N] = A[M,K] * B[K,N], all row-major ----------
// BM=128 BN=128 BK=8, 256 threads, 8x8 register tile. M%128==N%128==K%8==0.
__global__ __launch_bounds__(256)
void gemm_kernel(const float* __restrict__ A, const float* __restrict__ Bm,
                 float* __restrict__ C, int M, int N, int K) {
    const int BM = 128, BN = 128, BK = 8, TM = 8, TN = 8;
    __shared__ float As[BK][BM];
    __shared__ float Bs[BK][BN];
    int tid = threadIdx.x;
    int brow = blockIdx.y * BM;
    int bcol = blockIdx.x * BN;
    int tcol = (tid % (BN / TN)) * TN;   // 0..120 step 8
    int trow = (tid / (BN / TN)) * TM;   // 0..120 step 8
    float acc[TM][TN];
    #pragma unroll
    for (int i = 0; i < TM; i++)
        #pragma unroll
        for (int j = 0; j < TN; j++) acc[i][j] = 0.f;

    int aRow = tid >> 1;            // 0..127
    int aCol = (tid & 1) * 4;       // 0 or 4
    int bRow = tid >> 5;            // 0..7
    int bCol = (tid & 31) * 4;      // 0..124

    const float* Ap = A + (size_t)brow * K;
    const float* Bp = Bm + bcol;

    for (int k0 = 0; k0 < K; k0 += BK) {
        float4 a4 = *(const float4*)(Ap + (size_t)aRow * K + k0 + aCol);
        As[aCol + 0][aRow] = a4.x;
        As[aCol + 1][aRow] = a4.y;
        As[aCol + 2][aRow] = a4.z;
        As[aCol + 3][aRow] = a4.w;
        float4 b4 = *(const float4*)(Bp + (size_t)(k0 + bRow) * N + bCol);
        *(float4*)&Bs[bRow][bCol] = b4;
        __syncthreads();
        #pragma unroll
        for (int kk = 0; kk < BK; kk++) {
            float ar[TM], br[TN];
            #pragma unroll
            for (int i = 0; i < TM; i++) ar[i] = As[kk][trow + i];
            #pragma unroll
            for (int j = 0; j < TN; j++) br[j] = Bs[kk][tcol + j];
            #pragma unroll
            for (int i = 0; i < TM; i++)
                #pragma unroll
                for (int j = 0; j < TN; j++)
                    acc[i][j] = fmaf(ar[i], br[j], acc[i][j]);
        }
        __syncthreads();
    }
    #pragma unroll
    for (int i = 0; i < TM; i++) {
        size_t crow = (size_t)(brow + trow + i);
        #pragma unroll
        for (int j = 0; j < TN; j += 4) {
            float4 v = make_float4(acc[i][j], acc[i][j + 1], acc[i][j + 2], acc[i][j + 3]);
            *(float4*)&C[crow * N + bcol + tcol + j] = v;
        }
    }
}

// ---------- attention over G=18 connections, warp-per-(token,head) ----------
__global__ __launch_bounds__(256)
void attn_kernel(const float* __restrict__ q, const float* __restrict__ key,
                 const float* __restrict__ val, float* __restrict__ out) {
    int bs = blockIdx.x;               // 0..8191
    int head = threadIdx.x >> 5;       // 0..7
    int lane = threadIdx.x & 31;

    const float2 qv = *(const float2*)(q + (size_t)bs * HH + head * DD + 2 * lane);

    float sc[GG];
    const float* kb = key + (size_t)bs * GH + head * DD;
    #pragma unroll
    for (int j = 0; j < GG; j++) {
        float2 kv = *(const float2*)(kb + j * KDIM + 2 * lane);
        float s = qv.x * kv.x + qv.y * kv.y;
        s += __shfl_xor_sync(0xFFFFFFFFu, s, 16);
        s += __shfl_xor_sync(0xFFFFFFFFu, s, 8);
        s += __shfl_xor_sync(0xFFFFFFFFu, s, 4);
        s += __shfl_xor_sync(0xFFFFFFFFu, s, 2);
        s += __shfl_xor_sync(0xFFFFFFFFu, s, 1);
        sc[j] = s * 0.125f;   // 1/sqrt(64)
    }
    float m = sc[0];
    #pragma unroll
    for (int j = 1; j < GG; j++) m = fmaxf(m, sc[j]);
    float sum = 0.f;
    #pragma unroll
    for (int j = 0; j < GG; j++) { sc[j] = __expf(sc[j] - m); sum += sc[j]; }
    float inv = 1.f / sum;

    float ox = 0.f, oy = 0.f;
    const float* vb = val + (size_t)bs * GH + head * DD;
    #pragma unroll
    for (int j = 0; j < GG; j++) {
        float2 vv = *(const float2*)(vb + j * KDIM + 2 * lane);
        ox = fmaf(sc[j], vv.x, ox);
        oy = fmaf(sc[j], vv.y, oy);
    }
    float2 o = make_float2(ox * inv, oy * inv);
    *(float2*)(out + (size_t)bs * HH + head * DD + 2 * lane) = o;
}

// ---------- launch ----------
extern "C" void kernel_launch(void* const* d_in, const int* in_sizes, int n_in,
                              void* d_out, int out_size) {
    const float* hidden = (const float*)d_in[0];
    const void*  conn   = d_in[1];
    const float* Wq     = (const float*)d_in[2];
    const float* Wk     = (const float*)d_in[3];
    const float* Wv     = (const float*)d_in[4];
    const float* Wo     = (const float*)d_in[5];
    float* out = (float*)d_out;

    float *pA, *pKey, *pVal, *pQ, *pAttn;
    cudaGetSymbolAddress((void**)&pA,    g_A);
    cudaGetSymbolAddress((void**)&pKey,  g_key);
    cudaGetSymbolAddress((void**)&pVal,  g_val);
    cudaGetSymbolAddress((void**)&pQ,    g_q);
    cudaGetSymbolAddress((void**)&pAttn, g_attn);

    // 1) int width detection for connections
    detect_kernel<<<1, 32>>>((const int*)conn);

    // 2) gather A[8192, 9216]
    {
        size_t total = (size_t)MTOK * GG * (HH / 4);   // 18,874,368 float4s
        int threads = 256;
        int blocks = (int)((total + threads - 1) / threads);
        gather_kernel<<<blocks, threads>>>((const float4*)hidden, conn, (float4*)pA);
    }

    // 3) query = hidden @ Wq : [8192,512] x [512,512]
    {
        dim3 grid(HH / 128, MTOK / 128);
        gemm_kernel<<<grid, 256>>>(hidden, Wq, pQ, MTOK, HH, HH);
    }

    // 4) key = A @ Wk, value = A @ Wv : [8192,9216] x [9216,9216]
    {
        dim3 grid(GH / 128, MTOK / 128);
        gemm_kernel<<<grid, 256>>>(pA, Wk, pKey, MTOK, GH, GH);
        gemm_kernel<<<grid, 256>>>(pA, Wv, pVal, MTOK, GH, GH);
    }

    // 5) attention
    attn_kernel<<<MTOK, 256>>>(pQ, pKey, pVal, pAttn);

    // 6) out = attn @ Wo : [8192,512] x [512,512]
    {
        dim3 grid(HH / 128, MTOK / 128);
        gemm_kernel<<<grid, 256>>>(pAttn, Wo, out, MTOK, HH, HH);
    }
}

// round 3
// speedup vs baseline: 16.3082x; 16.3082x over previous
#include <cuda_runtime.h>
#include <cuda_fp16.h>
#include <cstdint>

// Problem constants
#define BB 2
#define SS 4096
#define HH 512
#define GG 18
#define NHEAD 8
#define DD 64
#define GH (GG*HH)        // 9216
#define MTOK (BB*SS)      // 8192
#define KDIM (NHEAD*DD)   // 512

// mma GEMM config
#define BKM 128
#define BKN 128
#define BKK 32
#define NKT (GH/BKK)      // 288
#define MT  (MTOK/BKM)    // 64
#define NT  (GH/BKN)      // 72
#define GROUPM 8
#define STAGES 4
#define SMEM_STAGE 16384          // A 8KB + B 8KB
#define SMEM_BYTES (STAGES*SMEM_STAGE)   // 65536

// ---------- static device scratch ----------
__device__ __half g_Ah[(size_t)MTOK * GH];    // gathered, fp16  (151MB)
__device__ __half g_Wkt[(size_t)GH * GH];     // Wk^T fp16 [N,K] (170MB)
__device__ __half g_Wvt[(size_t)GH * GH];
__device__ float  g_key[(size_t)MTOK * GH];   // 302MB
__device__ float  g_val[(size_t)MTOK * GH];   // 302MB
__device__ float  g_q[(size_t)MTOK * HH];
__device__ float  g_attn[(size_t)MTOK * HH];
__device__ int    g_is64;

// ---------- helpers ----------
__device__ __forceinline__ uint32_t smem_u32(const void* p) {
    uint32_t a;
    asm("{ .reg .u64 t; cvta.to.shared.u64 t, %1; cvt.u32.u64 %0, t; }" : "=r"(a) : "l"(p));
    return a;
}
__device__ __forceinline__ void cp16(uint32_t saddr, const void* gptr) {
    asm volatile("cp.async.cg.shared.global [%0], [%1], 16;" :: "r"(saddr), "l"(gptr) : "memory");
}
__device__ __forceinline__ void cp_commit() { asm volatile("cp.async.commit_group;" ::: "memory"); }
__device__ __forceinline__ void cp_wait2()  { asm volatile("cp.async.wait_group 2;" ::: "memory"); }

// swizzled smem offset for [128 rows][32 halfs] tile, rows of 4x16B chunks.
// 128B line = 2 rows; chunk position permuted so any 8-consecutive-row
// ldmatrix phase hits 8 distinct 16B bank groups.
__device__ __forceinline__ uint32_t swoff(int r, int ch) {
    return (uint32_t)(((r >> 1) << 7) + ((((r & 1) << 2) + (ch ^ ((r >> 1) & 3))) << 4));
}
__device__ __forceinline__ void ldsm4(uint32_t& r0, uint32_t& r1, uint32_t& r2, uint32_t& r3,
                                      uint32_t addr) {
    asm volatile("ldmatrix.sync.aligned.m8n8.x4.shared.b16 {%0,%1,%2,%3}, [%4];"
                 : "=r"(r0), "=r"(r1), "=r"(r2), "=r"(r3) : "r"(addr));
}
__device__ __forceinline__ void mma16816(float* d, const uint32_t* a, const uint32_t* b) {
    asm volatile(
        "mma.sync.aligned.m16n8k16.row.col.f32.f16.f16.f32 "
        "{%0,%1,%2,%3}, {%4,%5,%6,%7}, {%8,%9}, {%0,%1,%2,%3};"
        : "+f"(d[0]), "+f"(d[1]), "+f"(d[2]), "+f"(d[3])
        : "r"(a[0]), "r"(a[1]), "r"(a[2]), "r"(a[3]), "r"(b[0]), "r"(b[1]));
}

// ---------- detect int width of connections ----------
__global__ void detect_kernel(const int* __restrict__ conn) {
    if (threadIdx.x == 0 && blockIdx.x == 0) {
        int is64 = 1;
        #pragma unroll
        for (int i = 0; i < 64; i++) {
            if (conn[2 * i + 1] != 0) { is64 = 0; break; }
        }
        g_is64 = is64;
    }
}

// ---------- gather -> fp16 ----------
__global__ void gather_kernel(const float4* __restrict__ hidden,
                              const void* __restrict__ conn,
                              uint2* __restrict__ A) {
    size_t t = (size_t)blockIdx.x * blockDim.x + threadIdx.x;
    const size_t total = (size_t)MTOK * GG * (HH / 4);
    if (t >= total) return;
    int h4 = (int)(t & 127);
    size_t row = t >> 7;
    size_t bs = row / GG;
    int b = (int)(bs / SS);
    long long c;
    if (g_is64) c = ((const long long*)conn)[row];
    else        c = (long long)((const int*)conn)[row];
    float4 v = make_float4(0.f, 0.f, 0.f, 0.f);
    if (c >= 0) {
        if (c > SS - 1) c = SS - 1;
        v = hidden[((size_t)b * SS + (size_t)c) * (HH / 4) + h4];
    }
    union { __half2 h[2]; uint2 u; } pk;
    pk.h[0] = __floats2half2_rn(v.x, v.y);
    pk.h[1] = __floats2half2_rn(v.z, v.w);
    A[t] = pk.u;
}

// ---------- transpose [K,N] fp32 -> [N,K] fp16 ----------
__global__ __launch_bounds__(256)
void transpose_h_kernel(const float* __restrict__ src, __half* __restrict__ dst) {
    __shared__ float tile[32][33];
    int bn = blockIdx.x * 32;
    int bk = blockIdx.y * 32;
    int tx = threadIdx.x & 31, ty = threadIdx.x >> 5;
    #pragma unroll
    for (int i = 0; i < 4; i++) {
        int k = bk + ty + i * 8;
        tile[ty + i * 8][tx] = src[(size_t)k * GH + bn + tx];
    }
    __syncthreads();
    #pragma unroll
    for (int i = 0; i < 4; i++) {
        int n = bn + ty + i * 8;
        dst[(size_t)n * GH + bk + tx] = __float2half_rn(tile[tx][ty + i * 8]);
    }
}

// ---------- fp16 tensor-core GEMM: C[M,N] = A[M,K] * Bt[N,K]^T ----------
__global__ __launch_bounds__(256, 2)
void gemm_mma_kernel(const __half* __restrict__ A, const __half* __restrict__ Bt,
                     float* __restrict__ C) {
    extern __shared__ char smem[];
    uint32_t sbase = smem_u32(smem);
    int tid = threadIdx.x;
    int lane = tid & 31, w = tid >> 5;
    int wm = w >> 2, wn = w & 3;          // warps 2 (m) x 4 (n)

    // grouped rasterization for L2 reuse
    int pid = blockIdx.x;
    int per_g = GROUPM * NT;
    int g = pid / per_g;
    int rem = pid - g * per_g;
    int m_id = g * GROUPM + (rem % GROUPM);
    int n_id = rem / GROUPM;

    const __half* Ab = A + (size_t)m_id * BKM * GH;
    const __half* Bb = Bt + (size_t)n_id * BKN * GH;

    // per-thread load coords (2 chunks of A + 2 of B per stage)
    int c0 = tid, c1 = tid + 256;
    int r0 = c0 >> 2, ch0 = c0 & 3;
    int r1 = c1 >> 2, ch1 = c1 & 3;
    uint32_t so0 = swoff(r0, ch0), so1 = swoff(r1, ch1);

    #define LOAD_TILE(s, kt)                                                   \
    do {                                                                       \
        uint32_t sA_ = sbase + (s) * SMEM_STAGE;                               \
        uint32_t sB_ = sA_ + 8192;                                             \
        int k0_ = (kt) * BKK;                                                  \
        cp16(sA_ + so0, Ab + (size_t)r0 * GH + k0_ + ch0 * 8);                 \
        cp16(sA_ + so1, Ab + (size_t)r1 * GH + k0_ + ch1 * 8);                 \
        cp16(sB_ + so0, Bb + (size_t)r0 * GH + k0_ + ch0 * 8);                 \
        cp16(sB_ + so1, Bb + (size_t)r1 * GH + k0_ + ch1 * 8);                 \
    } while (0)

    LOAD_TILE(0, 0); cp_commit();
    LOAD_TILE(1, 1); cp_commit();
    LOAD_TILE(2, 2); cp_commit();

    float acc[4][4][4] = {};

    // precompute ldmatrix row components
    int a_row_base = wm * 64 + ((lane >> 3) & 1) * 8 + (lane & 7);
    int a_ch_base  = (lane >> 4);                 // +kf*2
    int b_row_base = wn * 32 + ((lane >> 4) & 1) * 8 + (lane & 7);
    int b_ch_base  = ((lane >> 3) & 1);           // +kf*2

    for (int kt = 0; kt < NKT; kt++) {
        int s = kt & 3;
        cp_wait2();
        __syncthreads();
        uint32_t sA = sbase + s * SMEM_STAGE;
        uint32_t sB = sA + 8192;

        #pragma unroll
        for (int kf = 0; kf < 2; kf++) {
            uint32_t af[4][4];
            uint32_t bf[4][2];
            #pragma unroll
            for (int mf = 0; mf < 4; mf++) {
                int row = a_row_base + mf * 16;
                int ch = a_ch_base + kf * 2;
                ldsm4(af[mf][0], af[mf][1], af[mf][2], af[mf][3], sA + swoff(row, ch));
            }
            #pragma unroll
            for (int np = 0; np < 2; np++) {
                int row = b_row_base + np * 16;
                int ch = b_ch_base + kf * 2;
                uint32_t q0, q1, q2, q3;
                ldsm4(q0, q1, q2, q3, sB + swoff(row, ch));
                bf[np * 2][0] = q0;     bf[np * 2][1] = q1;
                bf[np * 2 + 1][0] = q2; bf[np * 2 + 1][1] = q3;
            }
            #pragma unroll
            for (int mf = 0; mf < 4; mf++)
                #pragma unroll
                for (int nf = 0; nf < 4; nf++)
                    mma16816(acc[mf][nf], af[mf], bf[nf]);
        }

        if (kt + 3 < NKT) LOAD_TILE((kt + 3) & 3, kt + 3);
        cp_commit();
    }

    // epilogue
    size_t cm = (size_t)m_id * BKM + wm * 64;
    size_t cn = (size_t)n_id * BKN + wn * 32;
    #pragma unroll
    for (int mf = 0; mf < 4; mf++) {
        #pragma unroll
        for (int nf = 0; nf < 4; nf++) {
            size_t row = cm + mf * 16 + (lane >> 2);
            size_t col = cn + nf * 8 + (lane & 3) * 2;
            *(float2*)&C[row * GH + col] = make_float2(acc[mf][nf][0], acc[mf][nf][1]);
            *(float2*)&C[(row + 8) * GH + col] = make_float2(acc[mf][nf][2], acc[mf][nf][3]);
        }
    }
    #undef LOAD_TILE
}

// ---------- fp32 SIMT GEMM for the small projections ----------
__global__ __launch_bounds__(256)
void gemm_kernel(const float* __restrict__ A, const float* __restrict__ Bm,
                 float* __restrict__ C, int M, int N, int K) {
    const int BM = 128, BN = 128, BK = 8, TM = 8, TN = 8;
    __shared__ float As[BK][BM];
    __shared__ float Bs[BK][BN];
    int tid = threadIdx.x;
    int brow = blockIdx.y * BM;
    int bcol = blockIdx.x * BN;
    int tcol = (tid % (BN / TN)) * TN;
    int trow = (tid / (BN / TN)) * TM;
    float acc[TM][TN];
    #pragma unroll
    for (int i = 0; i < TM; i++)
        #pragma unroll
        for (int j = 0; j < TN; j++) acc[i][j] = 0.f;

    int aRow = tid >> 1;
    int aCol = (tid & 1) * 4;
    int bRow = tid >> 5;
    int bCol = (tid & 31) * 4;

    const float* Ap = A + (size_t)brow * K;
    const float* Bp = Bm + bcol;

    for (int k0 = 0; k0 < K; k0 += BK) {
        float4 a4 = *(const float4*)(Ap + (size_t)aRow * K + k0 + aCol);
        As[aCol + 0][aRow] = a4.x;
        As[aCol + 1][aRow] = a4.y;
        As[aCol + 2][aRow] = a4.z;
        As[aCol + 3][aRow] = a4.w;
        float4 b4 = *(const float4*)(Bp + (size_t)(k0 + bRow) * N + bCol);
        *(float4*)&Bs[bRow][bCol] = b4;
        __syncthreads();
        #pragma unroll
        for (int kk = 0; kk < BK; kk++) {
            float ar[TM], br[TN];
            #pragma unroll
            for (int i = 0; i < TM; i++) ar[i] = As[kk][trow + i];
            #pragma unroll
            for (int j = 0; j < TN; j++) br[j] = Bs[kk][tcol + j];
            #pragma unroll
            for (int i = 0; i < TM; i++)
                #pragma unroll
                for (int j = 0; j < TN; j++)
                    acc[i][j] = fmaf(ar[i], br[j], acc[i][j]);
        }
        __syncthreads();
    }
    #pragma unroll
    for (int i = 0; i < TM; i++) {
        size_t crow = (size_t)(brow + trow + i);
        #pragma unroll
        for (int j = 0; j < TN; j += 4) {
            float4 v = make_float4(acc[i][j], acc[i][j + 1], acc[i][j + 2], acc[i][j + 3]);
            *(float4*)&C[crow * N + bcol + tcol + j] = v;
        }
    }
}

// ---------- attention over G=18 connections ----------
__global__ __launch_bounds__(256)
void attn_kernel(const float* __restrict__ q, const float* __restrict__ key,
                 const float* __restrict__ val, float* __restrict__ out) {
    int bs = blockIdx.x;
    int head = threadIdx.x >> 5;
    int lane = threadIdx.x & 31;

    const float2 qv = *(const float2*)(q + (size_t)bs * HH + head * DD + 2 * lane);

    float sc[GG];
    const float* kb = key + (size_t)bs * GH + head * DD;
    #pragma unroll
    for (int j = 0; j < GG; j++) {
        float2 kv = *(const float2*)(kb + j * KDIM + 2 * lane);
        float s = qv.x * kv.x + qv.y * kv.y;
        s += __shfl_xor_sync(0xFFFFFFFFu, s, 16);
        s += __shfl_xor_sync(0xFFFFFFFFu, s, 8);
        s += __shfl_xor_sync(0xFFFFFFFFu, s, 4);
        s += __shfl_xor_sync(0xFFFFFFFFu, s, 2);
        s += __shfl_xor_sync(0xFFFFFFFFu, s, 1);
        sc[j] = s * 0.125f;
    }
    float m = sc[0];
    #pragma unroll
    for (int j = 1; j < GG; j++) m = fmaxf(m, sc[j]);
    float sum = 0.f;
    #pragma unroll
    for (int j = 0; j < GG; j++) { sc[j] = __expf(sc[j] - m); sum += sc[j]; }
    float inv = 1.f / sum;

    float ox = 0.f, oy = 0.f;
    const float* vb = val + (size_t)bs * GH + head * DD;
    #pragma unroll
    for (int j = 0; j < GG; j++) {
        float2 vv = *(const float2*)(vb + j * KDIM + 2 * lane);
        ox = fmaf(sc[j], vv.x, ox);
        oy = fmaf(sc[j], vv.y, oy);
    }
    float2 o = make_float2(ox * inv, oy * inv);
    *(float2*)(out + (size_t)bs * HH + head * DD + 2 * lane) = o;
}

// ---------- launch ----------
extern "C" void kernel_launch(void* const* d_in, const int* in_sizes, int n_in,
                              void* d_out, int out_size) {
    const float* hidden = (const float*)d_in[0];
    const void*  conn   = d_in[1];
    const float* Wq     = (const float*)d_in[2];
    const float* Wk     = (const float*)d_in[3];
    const float* Wv     = (const float*)d_in[4];
    const float* Wo     = (const float*)d_in[5];
    float* out = (float*)d_out;

    __half *pAh, *pWkt, *pWvt;
    float *pKey, *pVal, *pQ, *pAttn;
    cudaGetSymbolAddress((void**)&pAh,   g_Ah);
    cudaGetSymbolAddress((void**)&pWkt,  g_Wkt);
    cudaGetSymbolAddress((void**)&pWvt,  g_Wvt);
    cudaGetSymbolAddress((void**)&pKey,  g_key);
    cudaGetSymbolAddress((void**)&pVal,  g_val);
    cudaGetSymbolAddress((void**)&pQ,    g_q);
    cudaGetSymbolAddress((void**)&pAttn, g_attn);

    cudaFuncSetAttribute(gemm_mma_kernel, cudaFuncAttributeMaxDynamicSharedMemorySize, SMEM_BYTES);

    // 1) int width detection
    detect_kernel<<<1, 32>>>((const int*)conn);

    // 2) gather A[8192, 9216] -> fp16
    {
        size_t total = (size_t)MTOK * GG * (HH / 4);
        int threads = 256;
        int blocks = (int)((total + threads - 1) / threads);
        gather_kernel<<<blocks, threads>>>((const float4*)hidden, conn, (uint2*)pAh);
    }

    // 3) transpose weights [K,N] -> [N,K] fp16
    {
        dim3 grid(GH / 32, GH / 32);
        transpose_h_kernel<<<grid, 256>>>(Wk, pWkt);
        transpose_h_kernel<<<grid, 256>>>(Wv, pWvt);
    }

    // 4) query = hidden @ Wq (fp32 SIMT)
    {
        dim3 grid(HH / 128, MTOK / 128);
        gemm_kernel<<<grid, 256>>>(hidden, Wq, pQ, MTOK, HH, HH);
    }

    // 5) key/value: fp16 mma GEMM [8192,9216] x [9216,9216]
    gemm_mma_kernel<<<MT * NT, 256, SMEM_BYTES>>>(pAh, pWkt, pKey);
    gemm_mma_kernel<<<MT * NT, 256, SMEM_BYTES>>>(pAh, pWvt, pVal);

    // 6) attention
    attn_kernel<<<MTOK, 256>>>(pQ, pKey, pVal, pAttn);

    // 7) out = attn @ Wo (fp32 SIMT)
    {
        dim3 grid(HH / 128, MTOK / 128);
        gemm_kernel<<<grid, 256>>>(pAttn, Wo, out, MTOK, HH, HH);
    }
}